// round 13
// baseline (speedup 1.0000x reference)
#include <cuda_runtime.h>
#include <cstddef>

#define Bq 256
#define Sq 4096
#define Hq 64
#define Cq 32            // chunks along S
#define Lq (Sq / Cq)     // 128 elements per chunk
#define CPB 4            // chunks per block (1 per warp)
#define BPR (Cq / CPB)   // blocks per row = 8

// Per-(b,chunk,h) chunk aggregates. 2 MB, L2-resident.
__device__ __align__(16) float g_part[(size_t)Bq * Cq * Hq];
// Per-block done flags + per-row depart counters (zero at load; self-reset each launch).
__device__ unsigned g_flag[Bq * BPR];
__device__ unsigned g_depart[Bq];

typedef unsigned long long u64;

__device__ __forceinline__ u64 pack2(float lo, float hi) {
    u64 r; asm("mov.b64 %0, {%1, %2};" : "=l"(r) : "f"(lo), "f"(hi)); return r;
}
__device__ __forceinline__ void unpack2(u64 v, float& lo, float& hi) {
    asm("mov.b64 {%0, %1}, %2;" : "=f"(lo), "=f"(hi) : "l"(v));
}
__device__ __forceinline__ void unpack2u(u64 v, unsigned& lo, unsigned& hi) {
    asm("mov.b64 {%0, %1}, %2;" : "=r"(lo), "=r"(hi) : "l"(v));
}
__device__ __forceinline__ u64 fma2(u64 a, u64 b, u64 c) {
    u64 d; asm("fma.rn.f32x2 %0, %1, %2, %3;" : "=l"(d) : "l"(a), "l"(b), "l"(c)); return d;
}
__device__ __forceinline__ u64 add2(u64 a, u64 b) {
    u64 d; asm("add.rn.f32x2 %0, %1, %2;" : "=l"(d) : "l"(a), "l"(b)); return d;
}

#define MAGIC 12582912.0f        // 1.5*2^23
#define MAGIC_BITS 0x4B400000u   // bits(MAGIC + k) = MAGIC_BITS + k for integer k
#define HLq (Lq / 2)             // 64 steps per half-warp

// Block = 128 threads = 4 warps; warp w owns chunk c0+w.
// Warp split s-wise: lanes 0-15 do s in [0,64), lanes 16-31 do s in [64,128).
// Each lane owns 4 channels h0..h0+3 as two f32x2 chains -> STG.128 per step.
__global__ void __launch_bounds__(128) k_fused(const float* __restrict__ x,
                                               const float* __restrict__ W_e,
                                               const float* __restrict__ b_e,
                                               const float* __restrict__ omega,
                                               const float* __restrict__ W_r,
                                               const float* __restrict__ b_r,
                                               float* __restrict__ out,
                                               float* __restrict__ hseq) {
    __shared__ float4 shx[CPB * (Lq / 2)];  // {x_s,x_s,x_{s+1},x_{s+1}} per float4
    const int t  = threadIdx.x;
    const int w  = t >> 5;              // warp -> chunk within quad
    const int l  = t & 31;
    const int hh = l >> 4;              // s-half: 0 or 1
    const int li = l & 15;
    const int h0 = 4 * li;              // 4 channels per lane
    const int q  = blockIdx.x;
    const int b  = q >> 3;
    const int j  = q & (BPR - 1);       // block index within row
    const int c0 = j * CPB;
    const int c  = c0 + w;

    // ---- stage 512 contiguous floats (4 chunks), duplicated pairs for LDS.128 ----
    {
        const float4* xg = (const float4*)(x + (size_t)b * Sq + (size_t)c0 * Lq);
        float4 v = __ldg(xg + t);       // t = 0..127 covers 512 floats
        shx[2 * t + 0] = make_float4(v.x, v.x, v.y, v.y);
        shx[2 * t + 1] = make_float4(v.z, v.z, v.w, v.w);
    }

    const float INV_2PI = 0.15915494309189535f;
    const float TWO_PI  = 6.283185307179586f;
    const float we0 = W_e[h0]     * INV_2PI, we1 = W_e[h0 + 1] * INV_2PI;
    const float we2 = W_e[h0 + 2] * INV_2PI, we3 = W_e[h0 + 3] * INV_2PI;
    const float be0 = b_e[h0]     * INV_2PI, be1 = b_e[h0 + 1] * INV_2PI;
    const float be2 = b_e[h0 + 2] * INV_2PI, be3 = b_e[h0 + 3] * INV_2PI;
    const u64 weA = pack2(we0, we1), weB = pack2(we2, we3);
    const u64 beA = pack2(be0, be1), beB = pack2(be2, be3);
    const u64 omA = pack2(omega[h0] * TWO_PI,     omega[h0 + 1] * TWO_PI);
    const u64 omB = pack2(omega[h0 + 2] * TWO_PI, omega[h0 + 3] * TWO_PI);
    const u64 Mp    = pack2(MAGIC, MAGIC);
    const u64 negMp = pack2(-MAGIC, -MAGIC);
    const u64 nOne  = pack2(-1.0f, -1.0f);
    __syncthreads();

    // Half-warp's 32 x-pairs (covers its 64 s-steps).
    const float4* xs4 = shx + w * (Lq / 2) + hh * (HLq / 2);

    // ---- pass 1: half-chunk aggregates via separability (per chain) ----
    u64 aggA, aggB;
    {
        float psx = 0.0f;                       // Sum(x) over own half (all lanes identical)
        unsigned raA_lo = 0u, raA_hi = 0u;      // rint-bits accumulators, chain A
        unsigned raB_lo = 0u, raB_hi = 0u;      // chain B
#pragma unroll 8
        for (int jp = 0; jp < HLq / 2; ++jp) {
            float4 xv = xs4[jp];
            psx += xv.x + xv.z;
            u64 x2a = pack2(xv.x, xv.y);
            u64 x2b = pack2(xv.z, xv.w);
            u64 vaA = add2(fma2(x2a, weA, beA), Mp);
            u64 vbA = add2(fma2(x2b, weA, beA), Mp);
            u64 vaB = add2(fma2(x2a, weB, beB), Mp);
            u64 vbB = add2(fma2(x2b, weB, beB), Mp);
            unsigned u0, u1;
            unpack2u(vaA, u0, u1); raA_lo += u0; raA_hi += u1;
            unpack2u(vbA, u0, u1); raA_lo += u0; raA_hi += u1;
            unpack2u(vaB, u0, u1); raB_lo += u0; raB_hi += u1;
            unpack2u(vbB, u0, u1); raB_lo += u0; raB_hi += u1;
        }
        const unsigned sub = (unsigned)HLq * MAGIC_BITS;
        u64 ksA = pack2((float)(int)(raA_lo - sub), (float)(int)(raA_hi - sub));
        u64 ksB = pack2((float)(int)(raB_lo - sub), (float)(int)(raB_hi - sub));
        u64 hs2 = pack2(psx, psx);
        u64 beLA = pack2((float)HLq * be0, (float)HLq * be1);
        u64 beLB = pack2((float)HLq * be2, (float)HLq * be3);
        u64 tA = fma2(ksA, nOne, fma2(weA, hs2, beLA));
        u64 tB = fma2(ksB, nOne, fma2(weB, hs2, beLB));
        aggA = fma2(omA, tA, 0ull);
        aggB = fma2(omB, tB, 0ull);
    }

    // Exchange halves: other = the other s-half's aggregate (same channels).
    u64 othA = __shfl_xor_sync(0xffffffffu, aggA, 16);
    u64 othB = __shfl_xor_sync(0xffffffffu, aggB, 16);
    // Publish full-chunk aggregate (lanes 0-15 only, 256B coalesced STG.128).
    if (hh == 0) {
        ulonglong2 fullv;
        fullv.x = add2(aggA, othA);
        fullv.y = add2(aggB, othB);
        *(ulonglong2*)(g_part + ((size_t)(b << 5) + c) * Hq + h0) = fullv;
    }
    __syncthreads();

    // ---- depth-1 lookback: publish own flag; poll predecessors in parallel ----
    if (t == 0)
        asm volatile("st.global.release.gpu.u32 [%0], %1;"
                     :: "l"(&g_flag[b * BPR + j]), "r"(1u) : "memory");
    if (t < j) {    // thread t polls block t's flag (t = 0..j-1)
        const unsigned* fp = &g_flag[b * BPR + t];
        unsigned v;
        do {
            asm volatile("ld.global.acquire.gpu.u32 %0, [%1];"
                         : "=r"(v) : "l"(fp) : "memory");
            if (v) break;
            __nanosleep(40);
        } while (true);
    }
    __syncthreads();

    // ---- carry: ascending sum of preceding chunk aggregates (L2-resident) ----
    u64 accA = 0ull, accB = 0ull;
    {
        const float4* gp = (const float4*)(g_part + (size_t)(b << 5) * Hq + h0);
        float a0 = 0.f, a1 = 0.f, a2 = 0.f, a3 = 0.f;
        for (int cc = 0; cc < c; ++cc) {
            float4 v = __ldg(gp + cc * (Hq / 4));
            a0 += v.x; a1 += v.y; a2 += v.z; a3 += v.w;
        }
        accA = pack2(a0, a1);
        accB = pack2(a2, a3);
    }
    // Upper half additionally seeds with the lower half's aggregate.
    if (hh) {
        accA = add2(accA, othA);
        accB = add2(accB, othB);
    }

    // ---- pass 2: carry-seeded scan; LDS.128 = 2 steps; STG.128 per step ----
    char* hp = (char*)(hseq + ((size_t)b * Sq + (size_t)c * Lq + (size_t)hh * HLq) * Hq + h0);
#pragma unroll 8
    for (int jp = 0; jp < HLq / 2; ++jp) {
        float4 xv = xs4[jp];
        {
            u64 x2 = pack2(xv.x, xv.y);
            u64 uA = fma2(x2, weA, beA);
            u64 kA = add2(add2(uA, Mp), negMp);
            accA = fma2(omA, fma2(kA, nOne, uA), accA);
            u64 uB = fma2(x2, weB, beB);
            u64 kB = add2(add2(uB, Mp), negMp);
            accB = fma2(omB, fma2(kB, nOne, uB), accB);
            ulonglong2 stv; stv.x = accA; stv.y = accB;
            __stcs((ulonglong2*)(hp + (size_t)(2 * jp) * (Hq * 4)), stv);
        }
        {
            u64 x2 = pack2(xv.z, xv.w);
            u64 uA = fma2(x2, weA, beA);
            u64 kA = add2(add2(uA, Mp), negMp);
            accA = fma2(omA, fma2(kA, nOne, uA), accA);
            u64 uB = fma2(x2, weB, beB);
            u64 kB = add2(add2(uB, Mp), negMp);
            accB = fma2(omB, fma2(kB, nOne, uB), accB);
            ulonglong2 stv; stv.x = accA; stv.y = accB;
            __stcs((ulonglong2*)(hp + (size_t)(2 * jp + 1) * (Hq * 4)), stv);
        }
    }

    // ---- output head: chunk 31's upper half ends with ph[b][h0..h0+3] ----
    if (c == Cq - 1 && hh == 1) {
        float p0, p1, p2, p3;
        unpack2(accA, p0, p1);
        unpack2(accB, p2, p3);
        float tv;
        tv = p0 * W_r[2 * Hq + h0];
        tv = fmaf(cosf(p0), W_r[h0], tv);
        tv = fmaf(sinf(p0), W_r[Hq + h0], tv);
        tv = fmaf(p1, W_r[2 * Hq + h0 + 1], tv);
        tv = fmaf(cosf(p1), W_r[h0 + 1], tv);
        tv = fmaf(sinf(p1), W_r[Hq + h0 + 1], tv);
        tv = fmaf(p2, W_r[2 * Hq + h0 + 2], tv);
        tv = fmaf(cosf(p2), W_r[h0 + 2], tv);
        tv = fmaf(sinf(p2), W_r[Hq + h0 + 2], tv);
        tv = fmaf(p3, W_r[2 * Hq + h0 + 3], tv);
        tv = fmaf(cosf(p3), W_r[h0 + 3], tv);
        tv = fmaf(sinf(p3), W_r[Hq + h0 + 3], tv);
#pragma unroll
        for (int o = 8; o > 0; o >>= 1)
            tv += __shfl_down_sync(0xFFFF0000u, tv, o, 16);
        if (l == 16) out[b] = tv + b_r[0];
    }

    // ---- self-reset: last departing block of the row clears the flags ----
    __syncthreads();
    if (t == 0) {
        unsigned old = atomicAdd(&g_depart[b], 1u);
        if (old == (unsigned)(BPR - 1)) {
            g_depart[b] = 0u;
#pragma unroll
            for (int jj = 0; jj < BPR; ++jj)
                g_flag[b * BPR + jj] = 0u;
        }
    }
}

extern "C" void kernel_launch(void* const* d_in, const int* in_sizes, int n_in,
                              void* d_out, int out_size) {
    const float* x     = (const float*)d_in[0];
    const float* W_e   = (const float*)d_in[1];
    const float* b_e   = (const float*)d_in[2];
    const float* omega = (const float*)d_in[3];
    const float* W_r   = (const float*)d_in[4];
    const float* b_r   = (const float*)d_in[5];

    float* out  = (float*)d_out;        // out = B floats
    float* hseq = (float*)d_out + Bq;   // then Hseq = B*S*H floats

    k_fused<<<(Bq * Cq) / CPB, 128>>>(x, W_e, b_e, omega, W_r, b_r, out, hseq);
}

// round 14
// speedup vs baseline: 1.1392x; 1.1392x over previous
#include <cuda_runtime.h>
#include <cstddef>

#define Bq 256
#define Sq 4096
#define Hq 64
#define Cq 32            // chunks along S
#define Lq (Sq / Cq)     // 128 elements per chunk
#define CPB 4            // chunks per block (1 per warp)
#define BPR (Cq / CPB)   // blocks per row = 8

// Per-(b,chunk,h) chunk aggregates. 2 MB, L2-resident.
__device__ __align__(16) float g_part[(size_t)Bq * Cq * Hq];
// Self-resetting per-row barrier counters (zero at load; each launch restores zero).
__device__ unsigned g_arrive[Bq];
__device__ unsigned g_depart[Bq];

typedef unsigned long long u64;

__device__ __forceinline__ u64 pack2(float lo, float hi) {
    u64 r; asm("mov.b64 %0, {%1, %2};" : "=l"(r) : "f"(lo), "f"(hi)); return r;
}
__device__ __forceinline__ void unpack2(u64 v, float& lo, float& hi) {
    asm("mov.b64 {%0, %1}, %2;" : "=f"(lo), "=f"(hi) : "l"(v));
}
__device__ __forceinline__ void unpack2u(u64 v, unsigned& lo, unsigned& hi) {
    asm("mov.b64 {%0, %1}, %2;" : "=r"(lo), "=r"(hi) : "l"(v));
}
__device__ __forceinline__ u64 fma2(u64 a, u64 b, u64 c) {
    u64 d; asm("fma.rn.f32x2 %0, %1, %2, %3;" : "=l"(d) : "l"(a), "l"(b), "l"(c)); return d;
}
__device__ __forceinline__ u64 add2(u64 a, u64 b) {
    u64 d; asm("add.rn.f32x2 %0, %1, %2;" : "=l"(d) : "l"(a), "l"(b)); return d;
}

#define MAGIC 12582912.0f        // 1.5*2^23
#define MAGIC_BITS 0x4B400000u   // bits(MAGIC + k) = MAGIC_BITS + k for integer k
#define HLq (Lq / 2)             // 64 steps per half-warp

// Block = 128 threads = 4 warps; warp w owns chunk c0+w.
// Warp split s-wise: lanes 0-15 do s in [0,64), lanes 16-31 do s in [64,128).
// Each lane owns 4 channels h0..h0+3 as two f32x2 chains -> STG.128 per step.
__global__ void __launch_bounds__(128) k_fused(const float* __restrict__ x,
                                               const float* __restrict__ W_e,
                                               const float* __restrict__ b_e,
                                               const float* __restrict__ omega,
                                               const float* __restrict__ W_r,
                                               const float* __restrict__ b_r,
                                               float* __restrict__ out,
                                               float* __restrict__ hseq) {
    __shared__ float4 shx[CPB * (Lq / 2)];  // {x_s,x_s,x_{s+1},x_{s+1}} per float4
    const int t  = threadIdx.x;
    const int w  = t >> 5;              // warp -> chunk within quad
    const int l  = t & 31;
    const int hh = l >> 4;              // s-half: 0 or 1
    const int li = l & 15;
    const int h0 = 4 * li;              // 4 channels per lane
    const int q  = blockIdx.x;
    const int b  = q >> 3;
    const int c0 = (q & (BPR - 1)) * CPB;
    const int c  = c0 + w;

    // ---- stage 512 contiguous floats (4 chunks), duplicated pairs for LDS.128 ----
    {
        const float4* xg = (const float4*)(x + (size_t)b * Sq + (size_t)c0 * Lq);
        float4 v = __ldg(xg + t);       // t = 0..127 covers 512 floats
        shx[2 * t + 0] = make_float4(v.x, v.x, v.y, v.y);
        shx[2 * t + 1] = make_float4(v.z, v.z, v.w, v.w);
    }

    const float INV_2PI = 0.15915494309189535f;
    const float TWO_PI  = 6.283185307179586f;
    const float we0 = W_e[h0]     * INV_2PI, we1 = W_e[h0 + 1] * INV_2PI;
    const float we2 = W_e[h0 + 2] * INV_2PI, we3 = W_e[h0 + 3] * INV_2PI;
    const float be0 = b_e[h0]     * INV_2PI, be1 = b_e[h0 + 1] * INV_2PI;
    const float be2 = b_e[h0 + 2] * INV_2PI, be3 = b_e[h0 + 3] * INV_2PI;
    const u64 weA = pack2(we0, we1), weB = pack2(we2, we3);
    const u64 beA = pack2(be0, be1), beB = pack2(be2, be3);
    const u64 omA = pack2(omega[h0] * TWO_PI,     omega[h0 + 1] * TWO_PI);
    const u64 omB = pack2(omega[h0 + 2] * TWO_PI, omega[h0 + 3] * TWO_PI);
    const u64 Mp    = pack2(MAGIC, MAGIC);
    const u64 negMp = pack2(-MAGIC, -MAGIC);
    const u64 nOne  = pack2(-1.0f, -1.0f);
    __syncthreads();

    // Half-warp's 32 x-pairs (covers its 64 s-steps).
    const float4* xs4 = shx + w * (Lq / 2) + hh * (HLq / 2);

    // ---- pass 1: half-chunk aggregates via separability (per chain) ----
    u64 aggA, aggB;
    {
        float psx = 0.0f;                       // Sum(x) over own half (all lanes identical)
        unsigned raA_lo = 0u, raA_hi = 0u;      // rint-bits accumulators, chain A
        unsigned raB_lo = 0u, raB_hi = 0u;      // chain B
#pragma unroll 8
        for (int jp = 0; jp < HLq / 2; ++jp) {
            float4 xv = xs4[jp];
            psx += xv.x + xv.z;
            u64 x2a = pack2(xv.x, xv.y);
            u64 x2b = pack2(xv.z, xv.w);
            u64 vaA = add2(fma2(x2a, weA, beA), Mp);
            u64 vbA = add2(fma2(x2b, weA, beA), Mp);
            u64 vaB = add2(fma2(x2a, weB, beB), Mp);
            u64 vbB = add2(fma2(x2b, weB, beB), Mp);
            unsigned u0, u1;
            unpack2u(vaA, u0, u1); raA_lo += u0; raA_hi += u1;
            unpack2u(vbA, u0, u1); raA_lo += u0; raA_hi += u1;
            unpack2u(vaB, u0, u1); raB_lo += u0; raB_hi += u1;
            unpack2u(vbB, u0, u1); raB_lo += u0; raB_hi += u1;
        }
        const unsigned sub = (unsigned)HLq * MAGIC_BITS;
        u64 ksA = pack2((float)(int)(raA_lo - sub), (float)(int)(raA_hi - sub));
        u64 ksB = pack2((float)(int)(raB_lo - sub), (float)(int)(raB_hi - sub));
        u64 hs2 = pack2(psx, psx);
        u64 beLA = pack2((float)HLq * be0, (float)HLq * be1);
        u64 beLB = pack2((float)HLq * be2, (float)HLq * be3);
        u64 tA = fma2(ksA, nOne, fma2(weA, hs2, beLA));
        u64 tB = fma2(ksB, nOne, fma2(weB, hs2, beLB));
        aggA = fma2(omA, tA, 0ull);
        aggB = fma2(omB, tB, 0ull);
    }

    // Exchange halves: other = the other s-half's aggregate (same channels).
    u64 othA = __shfl_xor_sync(0xffffffffu, aggA, 16);
    u64 othB = __shfl_xor_sync(0xffffffffu, aggB, 16);
    // Publish full-chunk aggregate (lanes 0-15 only, 256B coalesced STG.128).
    if (hh == 0) {
        ulonglong2 fullv;
        fullv.x = add2(aggA, othA);
        fullv.y = add2(aggB, othB);
        *(ulonglong2*)(g_part + ((size_t)(b << 5) + c) * Hq + h0) = fullv;
    }
    __syncthreads();

    // ---- shallow per-row barrier (self-resetting) ----
    if (t == 0) {
        asm volatile("red.release.gpu.global.add.u32 [%0], %1;"
                     :: "l"(&g_arrive[b]), "r"(1u) : "memory");
        unsigned v;
        do {
            asm volatile("ld.global.acquire.gpu.u32 %0, [%1];"
                         : "=r"(v) : "l"(&g_arrive[b]) : "memory");
            if (v >= (unsigned)BPR) break;
            __nanosleep(40);
        } while (true);
        unsigned old = atomicAdd(&g_depart[b], 1u);
        if (old == (unsigned)(BPR - 1)) {
            g_arrive[b] = 0u;
            g_depart[b] = 0u;
        }
    }
    __syncthreads();

    // ---- carry: ascending sum of preceding chunk aggregates (L2-resident) ----
    u64 accA = 0ull, accB = 0ull;
    {
        const float4* gp = (const float4*)(g_part + (size_t)(b << 5) * Hq + h0);
        float a0 = 0.f, a1 = 0.f, a2 = 0.f, a3 = 0.f;
        for (int cc = 0; cc < c; ++cc) {
            float4 v = __ldg(gp + cc * (Hq / 4));
            a0 += v.x; a1 += v.y; a2 += v.z; a3 += v.w;
        }
        accA = pack2(a0, a1);
        accB = pack2(a2, a3);
    }
    // Upper half additionally seeds with the lower half's aggregate.
    if (hh) {
        accA = add2(accA, othA);
        accB = add2(accB, othB);
    }

    // ---- pass 2: carry-seeded scan; LDS.128 = 2 steps; STG.128 per step ----
    char* hp = (char*)(hseq + ((size_t)b * Sq + (size_t)c * Lq + (size_t)hh * HLq) * Hq + h0);
#pragma unroll 8
    for (int jp = 0; jp < HLq / 2; ++jp) {
        float4 xv = xs4[jp];
        {
            u64 x2 = pack2(xv.x, xv.y);
            u64 uA = fma2(x2, weA, beA);
            u64 kA = add2(add2(uA, Mp), negMp);
            accA = fma2(omA, fma2(kA, nOne, uA), accA);
            u64 uB = fma2(x2, weB, beB);
            u64 kB = add2(add2(uB, Mp), negMp);
            accB = fma2(omB, fma2(kB, nOne, uB), accB);
            ulonglong2 stv; stv.x = accA; stv.y = accB;
            __stcs((ulonglong2*)(hp + (size_t)(2 * jp) * (Hq * 4)), stv);
        }
        {
            u64 x2 = pack2(xv.z, xv.w);
            u64 uA = fma2(x2, weA, beA);
            u64 kA = add2(add2(uA, Mp), negMp);
            accA = fma2(omA, fma2(kA, nOne, uA), accA);
            u64 uB = fma2(x2, weB, beB);
            u64 kB = add2(add2(uB, Mp), negMp);
            accB = fma2(omB, fma2(kB, nOne, uB), accB);
            ulonglong2 stv; stv.x = accA; stv.y = accB;
            __stcs((ulonglong2*)(hp + (size_t)(2 * jp + 1) * (Hq * 4)), stv);
        }
    }

    // ---- output head: chunk 31's upper half ends with ph[b][h0..h0+3] ----
    if (c == Cq - 1 && hh == 1) {
        float p0, p1, p2, p3;
        unpack2(accA, p0, p1);
        unpack2(accB, p2, p3);
        float tv;
        tv = p0 * W_r[2 * Hq + h0];
        tv = fmaf(cosf(p0), W_r[h0], tv);
        tv = fmaf(sinf(p0), W_r[Hq + h0], tv);
        tv = fmaf(p1, W_r[2 * Hq + h0 + 1], tv);
        tv = fmaf(cosf(p1), W_r[h0 + 1], tv);
        tv = fmaf(sinf(p1), W_r[Hq + h0 + 1], tv);
        tv = fmaf(p2, W_r[2 * Hq + h0 + 2], tv);
        tv = fmaf(cosf(p2), W_r[h0 + 2], tv);
        tv = fmaf(sinf(p2), W_r[Hq + h0 + 2], tv);
        tv = fmaf(p3, W_r[2 * Hq + h0 + 3], tv);
        tv = fmaf(cosf(p3), W_r[h0 + 3], tv);
        tv = fmaf(sinf(p3), W_r[Hq + h0 + 3], tv);
#pragma unroll
        for (int o = 8; o > 0; o >>= 1)
            tv += __shfl_down_sync(0xFFFF0000u, tv, o, 16);
        if (l == 16) out[b] = tv + b_r[0];
    }
}

extern "C" void kernel_launch(void* const* d_in, const int* in_sizes, int n_in,
                              void* d_out, int out_size) {
    const float* x     = (const float*)d_in[0];
    const float* W_e   = (const float*)d_in[1];
    const float* b_e   = (const float*)d_in[2];
    const float* omega = (const float*)d_in[3];
    const float* W_r   = (const float*)d_in[4];
    const float* b_r   = (const float*)d_in[5];

    float* out  = (float*)d_out;        // out = B floats
    float* hseq = (float*)d_out + Bq;   // then Hseq = B*S*H floats

    k_fused<<<(Bq * Cq) / CPB, 128>>>(x, W_e, b_e, omega, W_r, b_r, out, hseq);
}

// round 15
// speedup vs baseline: 1.1601x; 1.0183x over previous
#include <cuda_runtime.h>
#include <cstddef>

#define Bq 256
#define Sq 4096
#define Hq 64
#define Cq 32            // chunks along S
#define Lq (Sq / Cq)     // 128 elements per chunk
#define CPB 8            // chunks per block (1 per warp)
#define BPR (Cq / CPB)   // blocks per row = 4
#define NT  (CPB * 32)   // 256 threads

// Per-(b,chunk,h) chunk aggregates. 2 MB, L2-resident.
__device__ __align__(16) float g_part[(size_t)Bq * Cq * Hq];
// Self-resetting per-row barrier counters (zero at load; each launch restores zero).
__device__ unsigned g_arrive[Bq];
__device__ unsigned g_depart[Bq];

typedef unsigned long long u64;

__device__ __forceinline__ u64 pack2(float lo, float hi) {
    u64 r; asm("mov.b64 %0, {%1, %2};" : "=l"(r) : "f"(lo), "f"(hi)); return r;
}
__device__ __forceinline__ void unpack2(u64 v, float& lo, float& hi) {
    asm("mov.b64 {%0, %1}, %2;" : "=f"(lo), "=f"(hi) : "l"(v));
}
__device__ __forceinline__ void unpack2u(u64 v, unsigned& lo, unsigned& hi) {
    asm("mov.b64 {%0, %1}, %2;" : "=r"(lo), "=r"(hi) : "l"(v));
}
__device__ __forceinline__ u64 fma2(u64 a, u64 b, u64 c) {
    u64 d; asm("fma.rn.f32x2 %0, %1, %2, %3;" : "=l"(d) : "l"(a), "l"(b), "l"(c)); return d;
}
__device__ __forceinline__ u64 add2(u64 a, u64 b) {
    u64 d; asm("add.rn.f32x2 %0, %1, %2;" : "=l"(d) : "l"(a), "l"(b)); return d;
}

#define MAGIC 12582912.0f        // 1.5*2^23
#define MAGIC_BITS 0x4B400000u   // bits(MAGIC + k) = MAGIC_BITS + k for integer k
#define HLq (Lq / 2)             // 64 steps per half-warp

// Block = 256 threads = 8 warps; warp w owns chunk c0+w.
// Warp split s-wise: lanes 0-15 do s in [0,64), lanes 16-31 do s in [64,128).
// Each lane owns 4 channels h0..h0+3 as two f32x2 chains -> STG.128 per step.
__global__ void __launch_bounds__(NT) k_fused(const float* __restrict__ x,
                                              const float* __restrict__ W_e,
                                              const float* __restrict__ b_e,
                                              const float* __restrict__ omega,
                                              const float* __restrict__ W_r,
                                              const float* __restrict__ b_r,
                                              float* __restrict__ out,
                                              float* __restrict__ hseq) {
    __shared__ float4 shx[CPB * (Lq / 2)];  // {x_s,x_s,x_{s+1},x_{s+1}} per float4
    const int t  = threadIdx.x;
    const int w  = t >> 5;              // warp -> chunk within group
    const int l  = t & 31;
    const int hh = l >> 4;              // s-half: 0 or 1
    const int li = l & 15;
    const int h0 = 4 * li;              // 4 channels per lane
    const int q  = blockIdx.x;
    const int b  = q >> 2;              // 4 blocks per row
    const int c0 = (q & (BPR - 1)) * CPB;
    const int c  = c0 + w;

    // ---- stage 1024 contiguous floats (8 chunks), duplicated pairs for LDS.128 ----
    {
        const float4* xg = (const float4*)(x + (size_t)b * Sq + (size_t)c0 * Lq);
        float4 v = __ldg(xg + t);       // t = 0..255 covers 1024 floats
        shx[2 * t + 0] = make_float4(v.x, v.x, v.y, v.y);
        shx[2 * t + 1] = make_float4(v.z, v.z, v.w, v.w);
    }

    const float INV_2PI = 0.15915494309189535f;
    const float TWO_PI  = 6.283185307179586f;
    const float we0 = W_e[h0]     * INV_2PI, we1 = W_e[h0 + 1] * INV_2PI;
    const float we2 = W_e[h0 + 2] * INV_2PI, we3 = W_e[h0 + 3] * INV_2PI;
    const float be0 = b_e[h0]     * INV_2PI, be1 = b_e[h0 + 1] * INV_2PI;
    const float be2 = b_e[h0 + 2] * INV_2PI, be3 = b_e[h0 + 3] * INV_2PI;
    const u64 weA = pack2(we0, we1), weB = pack2(we2, we3);
    const u64 beA = pack2(be0, be1), beB = pack2(be2, be3);
    const u64 omA = pack2(omega[h0] * TWO_PI,     omega[h0 + 1] * TWO_PI);
    const u64 omB = pack2(omega[h0 + 2] * TWO_PI, omega[h0 + 3] * TWO_PI);
    const u64 Mp    = pack2(MAGIC, MAGIC);
    const u64 negMp = pack2(-MAGIC, -MAGIC);
    const u64 nOne  = pack2(-1.0f, -1.0f);
    __syncthreads();

    // Half-warp's 32 x-pairs (covers its 64 s-steps).
    const float4* xs4 = shx + w * (Lq / 2) + hh * (HLq / 2);

    // ---- pass 1: half-chunk aggregates via separability (per chain) ----
    u64 aggA, aggB;
    {
        float psx = 0.0f;                       // Sum(x) over own half (all lanes identical)
        unsigned raA_lo = 0u, raA_hi = 0u;      // rint-bits accumulators, chain A
        unsigned raB_lo = 0u, raB_hi = 0u;      // chain B
#pragma unroll 8
        for (int jp = 0; jp < HLq / 2; ++jp) {
            float4 xv = xs4[jp];
            psx += xv.x + xv.z;
            u64 x2a = pack2(xv.x, xv.y);
            u64 x2b = pack2(xv.z, xv.w);
            u64 vaA = add2(fma2(x2a, weA, beA), Mp);
            u64 vbA = add2(fma2(x2b, weA, beA), Mp);
            u64 vaB = add2(fma2(x2a, weB, beB), Mp);
            u64 vbB = add2(fma2(x2b, weB, beB), Mp);
            unsigned u0, u1;
            unpack2u(vaA, u0, u1); raA_lo += u0; raA_hi += u1;
            unpack2u(vbA, u0, u1); raA_lo += u0; raA_hi += u1;
            unpack2u(vaB, u0, u1); raB_lo += u0; raB_hi += u1;
            unpack2u(vbB, u0, u1); raB_lo += u0; raB_hi += u1;
        }
        const unsigned sub = (unsigned)HLq * MAGIC_BITS;
        u64 ksA = pack2((float)(int)(raA_lo - sub), (float)(int)(raA_hi - sub));
        u64 ksB = pack2((float)(int)(raB_lo - sub), (float)(int)(raB_hi - sub));
        u64 hs2 = pack2(psx, psx);
        u64 beLA = pack2((float)HLq * be0, (float)HLq * be1);
        u64 beLB = pack2((float)HLq * be2, (float)HLq * be3);
        u64 tA = fma2(ksA, nOne, fma2(weA, hs2, beLA));
        u64 tB = fma2(ksB, nOne, fma2(weB, hs2, beLB));
        aggA = fma2(omA, tA, 0ull);
        aggB = fma2(omB, tB, 0ull);
    }

    // Exchange halves: other = the other s-half's aggregate (same channels).
    u64 othA = __shfl_xor_sync(0xffffffffu, aggA, 16);
    u64 othB = __shfl_xor_sync(0xffffffffu, aggB, 16);
    // Publish full-chunk aggregate (lanes 0-15 only, 256B coalesced STG.128).
    if (hh == 0) {
        ulonglong2 fullv;
        fullv.x = add2(aggA, othA);
        fullv.y = add2(aggB, othB);
        *(ulonglong2*)(g_part + ((size_t)(b << 5) + c) * Hq + h0) = fullv;
    }
    __syncthreads();

    // ---- shallow per-row barrier (self-resetting; 4 arrivals per row) ----
    if (t == 0) {
        asm volatile("red.release.gpu.global.add.u32 [%0], %1;"
                     :: "l"(&g_arrive[b]), "r"(1u) : "memory");
        unsigned v;
        do {
            asm volatile("ld.global.acquire.gpu.u32 %0, [%1];"
                         : "=r"(v) : "l"(&g_arrive[b]) : "memory");
            if (v >= (unsigned)BPR) break;
            __nanosleep(40);
        } while (true);
        unsigned old = atomicAdd(&g_depart[b], 1u);
        if (old == (unsigned)(BPR - 1)) {
            g_arrive[b] = 0u;
            g_depart[b] = 0u;
        }
    }
    __syncthreads();

    // ---- carry: ascending sum of preceding chunk aggregates (L2-resident) ----
    u64 accA = 0ull, accB = 0ull;
    {
        const float4* gp = (const float4*)(g_part + (size_t)(b << 5) * Hq + h0);
        float a0 = 0.f, a1 = 0.f, a2 = 0.f, a3 = 0.f;
        for (int cc = 0; cc < c; ++cc) {
            float4 v = __ldg(gp + cc * (Hq / 4));
            a0 += v.x; a1 += v.y; a2 += v.z; a3 += v.w;
        }
        accA = pack2(a0, a1);
        accB = pack2(a2, a3);
    }
    // Upper half additionally seeds with the lower half's aggregate.
    if (hh) {
        accA = add2(accA, othA);
        accB = add2(accB, othB);
    }

    // ---- pass 2: carry-seeded scan; LDS.128 = 2 steps; STG.128 per step ----
    char* hp = (char*)(hseq + ((size_t)b * Sq + (size_t)c * Lq + (size_t)hh * HLq) * Hq + h0);
#pragma unroll 8
    for (int jp = 0; jp < HLq / 2; ++jp) {
        float4 xv = xs4[jp];
        {
            u64 x2 = pack2(xv.x, xv.y);
            u64 uA = fma2(x2, weA, beA);
            u64 kA = add2(add2(uA, Mp), negMp);
            accA = fma2(omA, fma2(kA, nOne, uA), accA);
            u64 uB = fma2(x2, weB, beB);
            u64 kB = add2(add2(uB, Mp), negMp);
            accB = fma2(omB, fma2(kB, nOne, uB), accB);
            ulonglong2 stv; stv.x = accA; stv.y = accB;
            __stcs((ulonglong2*)(hp + (size_t)(2 * jp) * (Hq * 4)), stv);
        }
        {
            u64 x2 = pack2(xv.z, xv.w);
            u64 uA = fma2(x2, weA, beA);
            u64 kA = add2(add2(uA, Mp), negMp);
            accA = fma2(omA, fma2(kA, nOne, uA), accA);
            u64 uB = fma2(x2, weB, beB);
            u64 kB = add2(add2(uB, Mp), negMp);
            accB = fma2(omB, fma2(kB, nOne, uB), accB);
            ulonglong2 stv; stv.x = accA; stv.y = accB;
            __stcs((ulonglong2*)(hp + (size_t)(2 * jp + 1) * (Hq * 4)), stv);
        }
    }

    // ---- output head: chunk 31's upper half ends with ph[b][h0..h0+3] ----
    if (c == Cq - 1 && hh == 1) {
        float p0, p1, p2, p3;
        unpack2(accA, p0, p1);
        unpack2(accB, p2, p3);
        float tv;
        tv = p0 * W_r[2 * Hq + h0];
        tv = fmaf(cosf(p0), W_r[h0], tv);
        tv = fmaf(sinf(p0), W_r[Hq + h0], tv);
        tv = fmaf(p1, W_r[2 * Hq + h0 + 1], tv);
        tv = fmaf(cosf(p1), W_r[h0 + 1], tv);
        tv = fmaf(sinf(p1), W_r[Hq + h0 + 1], tv);
        tv = fmaf(p2, W_r[2 * Hq + h0 + 2], tv);
        tv = fmaf(cosf(p2), W_r[h0 + 2], tv);
        tv = fmaf(sinf(p2), W_r[Hq + h0 + 2], tv);
        tv = fmaf(p3, W_r[2 * Hq + h0 + 3], tv);
        tv = fmaf(cosf(p3), W_r[h0 + 3], tv);
        tv = fmaf(sinf(p3), W_r[Hq + h0 + 3], tv);
#pragma unroll
        for (int o = 8; o > 0; o >>= 1)
            tv += __shfl_down_sync(0xFFFF0000u, tv, o, 16);
        if (l == 16) out[b] = tv + b_r[0];
    }
}

extern "C" void kernel_launch(void* const* d_in, const int* in_sizes, int n_in,
                              void* d_out, int out_size) {
    const float* x     = (const float*)d_in[0];
    const float* W_e   = (const float*)d_in[1];
    const float* b_e   = (const float*)d_in[2];
    const float* omega = (const float*)d_in[3];
    const float* W_r   = (const float*)d_in[4];
    const float* b_r   = (const float*)d_in[5];

    float* out  = (float*)d_out;        // out = B floats
    float* hseq = (float*)d_out + Bq;   // then Hseq = B*S*H floats

    k_fused<<<(Bq * Cq) / CPB, NT>>>(x, W_e, b_e, omega, W_r, b_r, out, hseq);
}

// round 16
// speedup vs baseline: 1.1877x; 1.0239x over previous
#include <cuda_runtime.h>
#include <cstddef>

#define Bq 256
#define Sq 4096
#define Hq 64
#define Cq 32            // chunks along S
#define Lq (Sq / Cq)     // 128 elements per chunk
#define CPB 8            // chunks per block (1 per warp)
#define BPR (Cq / CPB)   // blocks per row = 4
#define NT  (CPB * 32)   // 256 threads

// Per-(b,block,h) BLOCK-level aggregate sums. 256 KB, L2-resident.
__device__ __align__(16) float g_bsum[(size_t)Bq * BPR * Hq];
// Self-resetting per-row barrier counters (zero at load; each launch restores zero).
__device__ unsigned g_arrive[Bq];
__device__ unsigned g_depart[Bq];

typedef unsigned long long u64;

__device__ __forceinline__ u64 pack2(float lo, float hi) {
    u64 r; asm("mov.b64 %0, {%1, %2};" : "=l"(r) : "f"(lo), "f"(hi)); return r;
}
__device__ __forceinline__ void unpack2(u64 v, float& lo, float& hi) {
    asm("mov.b64 {%0, %1}, %2;" : "=f"(lo), "=f"(hi) : "l"(v));
}
__device__ __forceinline__ void unpack2u(u64 v, unsigned& lo, unsigned& hi) {
    asm("mov.b64 {%0, %1}, %2;" : "=r"(lo), "=r"(hi) : "l"(v));
}
__device__ __forceinline__ u64 fma2(u64 a, u64 b, u64 c) {
    u64 d; asm("fma.rn.f32x2 %0, %1, %2, %3;" : "=l"(d) : "l"(a), "l"(b), "l"(c)); return d;
}
__device__ __forceinline__ u64 add2(u64 a, u64 b) {
    u64 d; asm("add.rn.f32x2 %0, %1, %2;" : "=l"(d) : "l"(a), "l"(b)); return d;
}

#define MAGIC 12582912.0f        // 1.5*2^23
#define MAGIC_BITS 0x4B400000u   // bits(MAGIC + k) = MAGIC_BITS + k for integer k
#define HLq (Lq / 2)             // 64 steps per half-warp

// Block = 256 threads = 8 warps; warp w owns chunk c0+w.
// Warp split s-wise: lanes 0-15 do s in [0,64), lanes 16-31 do s in [64,128).
// Each lane owns 4 channels h0..h0+3 as two f32x2 chains -> STG.128 per step.
__global__ void __launch_bounds__(NT) k_fused(const float* __restrict__ x,
                                              const float* __restrict__ W_e,
                                              const float* __restrict__ b_e,
                                              const float* __restrict__ omega,
                                              const float* __restrict__ W_r,
                                              const float* __restrict__ b_r,
                                              float* __restrict__ out,
                                              float* __restrict__ hseq) {
    __shared__ float4 shx[CPB * (Lq / 2)];  // {x_s,x_s,x_{s+1},x_{s+1}} per float4
    __shared__ float4 sh_agg[CPB][16];      // per-chunk aggregates, [w][li] = h0..h0+3
    const int t  = threadIdx.x;
    const int w  = t >> 5;              // warp -> chunk within group
    const int l  = t & 31;
    const int hh = l >> 4;              // s-half: 0 or 1
    const int li = l & 15;
    const int h0 = 4 * li;              // 4 channels per lane
    const int q  = blockIdx.x;
    const int b  = q >> 2;              // 4 blocks per row
    const int j  = q & (BPR - 1);       // block index within row
    const int c0 = j * CPB;
    const int c  = c0 + w;

    // ---- stage 1024 contiguous floats (8 chunks), duplicated pairs for LDS.128 ----
    {
        const float4* xg = (const float4*)(x + (size_t)b * Sq + (size_t)c0 * Lq);
        float4 v = __ldg(xg + t);       // t = 0..255 covers 1024 floats
        shx[2 * t + 0] = make_float4(v.x, v.x, v.y, v.y);
        shx[2 * t + 1] = make_float4(v.z, v.z, v.w, v.w);
    }

    const float INV_2PI = 0.15915494309189535f;
    const float TWO_PI  = 6.283185307179586f;
    const float we0 = W_e[h0]     * INV_2PI, we1 = W_e[h0 + 1] * INV_2PI;
    const float we2 = W_e[h0 + 2] * INV_2PI, we3 = W_e[h0 + 3] * INV_2PI;
    const float be0 = b_e[h0]     * INV_2PI, be1 = b_e[h0 + 1] * INV_2PI;
    const float be2 = b_e[h0 + 2] * INV_2PI, be3 = b_e[h0 + 3] * INV_2PI;
    const u64 weA = pack2(we0, we1), weB = pack2(we2, we3);
    const u64 beA = pack2(be0, be1), beB = pack2(be2, be3);
    const u64 omA = pack2(omega[h0] * TWO_PI,     omega[h0 + 1] * TWO_PI);
    const u64 omB = pack2(omega[h0 + 2] * TWO_PI, omega[h0 + 3] * TWO_PI);
    const u64 Mp    = pack2(MAGIC, MAGIC);
    const u64 negMp = pack2(-MAGIC, -MAGIC);
    const u64 nOne  = pack2(-1.0f, -1.0f);
    __syncthreads();

    // Half-warp's 32 x-pairs (covers its 64 s-steps).
    const float4* xs4 = shx + w * (Lq / 2) + hh * (HLq / 2);

    // ---- pass 1: half-chunk aggregates via separability (per chain) ----
    u64 aggA, aggB;
    {
        float psx = 0.0f;                       // Sum(x) over own half (all lanes identical)
        unsigned raA_lo = 0u, raA_hi = 0u;      // rint-bits accumulators, chain A
        unsigned raB_lo = 0u, raB_hi = 0u;      // chain B
#pragma unroll 8
        for (int jp = 0; jp < HLq / 2; ++jp) {
            float4 xv = xs4[jp];
            psx += xv.x + xv.z;
            u64 x2a = pack2(xv.x, xv.y);
            u64 x2b = pack2(xv.z, xv.w);
            u64 vaA = add2(fma2(x2a, weA, beA), Mp);
            u64 vbA = add2(fma2(x2b, weA, beA), Mp);
            u64 vaB = add2(fma2(x2a, weB, beB), Mp);
            u64 vbB = add2(fma2(x2b, weB, beB), Mp);
            unsigned u0, u1;
            unpack2u(vaA, u0, u1); raA_lo += u0; raA_hi += u1;
            unpack2u(vbA, u0, u1); raA_lo += u0; raA_hi += u1;
            unpack2u(vaB, u0, u1); raB_lo += u0; raB_hi += u1;
            unpack2u(vbB, u0, u1); raB_lo += u0; raB_hi += u1;
        }
        const unsigned sub = (unsigned)HLq * MAGIC_BITS;
        u64 ksA = pack2((float)(int)(raA_lo - sub), (float)(int)(raA_hi - sub));
        u64 ksB = pack2((float)(int)(raB_lo - sub), (float)(int)(raB_hi - sub));
        u64 hs2 = pack2(psx, psx);
        u64 beLA = pack2((float)HLq * be0, (float)HLq * be1);
        u64 beLB = pack2((float)HLq * be2, (float)HLq * be3);
        u64 tA = fma2(ksA, nOne, fma2(weA, hs2, beLA));
        u64 tB = fma2(ksB, nOne, fma2(weB, hs2, beLB));
        aggA = fma2(omA, tA, 0ull);
        aggB = fma2(omB, tB, 0ull);
    }

    // Exchange halves: other = the other s-half's aggregate (same channels).
    u64 othA = __shfl_xor_sync(0xffffffffu, aggA, 16);
    u64 othB = __shfl_xor_sync(0xffffffffu, aggB, 16);
    // Full-chunk aggregate into smem (lanes 0-15 only).
    if (hh == 0) {
        ulonglong2 fullv;
        fullv.x = add2(aggA, othA);
        fullv.y = add2(aggB, othB);
        *(ulonglong2*)&sh_agg[w][li] = fullv;
    }
    __syncthreads();

    // ---- block sum -> global (warp 0, lanes 0-15; 256B coalesced STG.128) ----
    if (t < 16) {
        float4 s = sh_agg[0][t];
#pragma unroll
        for (int ww = 1; ww < CPB; ++ww) {
            float4 v = sh_agg[ww][t];
            s.x += v.x; s.y += v.y; s.z += v.z; s.w += v.w;
        }
        *(float4*)(g_bsum + ((size_t)(b * BPR + j)) * Hq + 4 * t) = s;
    }
    __syncthreads();

    // ---- shallow per-row barrier (self-resetting; 4 arrivals per row) ----
    if (t == 0) {
        asm volatile("red.release.gpu.global.add.u32 [%0], %1;"
                     :: "l"(&g_arrive[b]), "r"(1u) : "memory");
        unsigned v;
        do {
            asm volatile("ld.global.acquire.gpu.u32 %0, [%1];"
                         : "=r"(v) : "l"(&g_arrive[b]) : "memory");
            if (v >= (unsigned)BPR) break;
            __nanosleep(40);
        } while (true);
        unsigned old = atomicAdd(&g_depart[b], 1u);
        if (old == (unsigned)(BPR - 1)) {
            g_arrive[b] = 0u;
            g_depart[b] = 0u;
        }
    }
    __syncthreads();

    // ---- hierarchical carry: <=3 predecessor block sums (L2) + <=7 smem aggs ----
    u64 accA, accB;
    {
        float a0 = 0.f, a1 = 0.f, a2 = 0.f, a3 = 0.f;
        const float4* gb = (const float4*)(g_bsum + (size_t)(b * BPR) * Hq + h0);
        for (int jj = 0; jj < j; ++jj) {
            float4 v = __ldg(gb + jj * (Hq / 4));
            a0 += v.x; a1 += v.y; a2 += v.z; a3 += v.w;
        }
#pragma unroll
        for (int ww = 0; ww < CPB; ++ww) {
            if (ww >= w) break;
            float4 v = sh_agg[ww][li];
            a0 += v.x; a1 += v.y; a2 += v.z; a3 += v.w;
        }
        accA = pack2(a0, a1);
        accB = pack2(a2, a3);
    }
    // Upper half additionally seeds with the lower half's aggregate.
    if (hh) {
        accA = add2(accA, othA);
        accB = add2(accB, othB);
    }

    // ---- pass 2: carry-seeded scan; LDS.128 = 2 steps; STG.128 per step ----
    char* hp = (char*)(hseq + ((size_t)b * Sq + (size_t)c * Lq + (size_t)hh * HLq) * Hq + h0);
#pragma unroll 8
    for (int jp = 0; jp < HLq / 2; ++jp) {
        float4 xv = xs4[jp];
        {
            u64 x2 = pack2(xv.x, xv.y);
            u64 uA = fma2(x2, weA, beA);
            u64 kA = add2(add2(uA, Mp), negMp);
            accA = fma2(omA, fma2(kA, nOne, uA), accA);
            u64 uB = fma2(x2, weB, beB);
            u64 kB = add2(add2(uB, Mp), negMp);
            accB = fma2(omB, fma2(kB, nOne, uB), accB);
            ulonglong2 stv; stv.x = accA; stv.y = accB;
            __stcs((ulonglong2*)(hp + (size_t)(2 * jp) * (Hq * 4)), stv);
        }
        {
            u64 x2 = pack2(xv.z, xv.w);
            u64 uA = fma2(x2, weA, beA);
            u64 kA = add2(add2(uA, Mp), negMp);
            accA = fma2(omA, fma2(kA, nOne, uA), accA);
            u64 uB = fma2(x2, weB, beB);
            u64 kB = add2(add2(uB, Mp), negMp);
            accB = fma2(omB, fma2(kB, nOne, uB), accB);
            ulonglong2 stv; stv.x = accA; stv.y = accB;
            __stcs((ulonglong2*)(hp + (size_t)(2 * jp + 1) * (Hq * 4)), stv);
        }
    }

    // ---- output head: chunk 31's upper half ends with ph[b][h0..h0+3] ----
    if (c == Cq - 1 && hh == 1) {
        float p0, p1, p2, p3;
        unpack2(accA, p0, p1);
        unpack2(accB, p2, p3);
        float tv;
        tv = p0 * W_r[2 * Hq + h0];
        tv = fmaf(cosf(p0), W_r[h0], tv);
        tv = fmaf(sinf(p0), W_r[Hq + h0], tv);
        tv = fmaf(p1, W_r[2 * Hq + h0 + 1], tv);
        tv = fmaf(cosf(p1), W_r[h0 + 1], tv);
        tv = fmaf(sinf(p1), W_r[Hq + h0 + 1], tv);
        tv = fmaf(p2, W_r[2 * Hq + h0 + 2], tv);
        tv = fmaf(cosf(p2), W_r[h0 + 2], tv);
        tv = fmaf(sinf(p2), W_r[Hq + h0 + 2], tv);
        tv = fmaf(p3, W_r[2 * Hq + h0 + 3], tv);
        tv = fmaf(cosf(p3), W_r[h0 + 3], tv);
        tv = fmaf(sinf(p3), W_r[Hq + h0 + 3], tv);
#pragma unroll
        for (int o = 8; o > 0; o >>= 1)
            tv += __shfl_down_sync(0xFFFF0000u, tv, o, 16);
        if (l == 16) out[b] = tv + b_r[0];
    }
}

extern "C" void kernel_launch(void* const* d_in, const int* in_sizes, int n_in,
                              void* d_out, int out_size) {
    const float* x     = (const float*)d_in[0];
    const float* W_e   = (const float*)d_in[1];
    const float* b_e   = (const float*)d_in[2];
    const float* omega = (const float*)d_in[3];
    const float* W_r   = (const float*)d_in[4];
    const float* b_r   = (const float*)d_in[5];

    float* out  = (float*)d_out;        // out = B floats
    float* hseq = (float*)d_out + Bq;   // then Hseq = B*S*H floats

    k_fused<<<(Bq * Cq) / CPB, NT>>>(x, W_e, b_e, omega, W_r, b_r, out, hseq);
}